// round 5
// baseline (speedup 1.0000x reference)
#include <cuda_runtime.h>
#include <cuda_bf16.h>
#include <math.h>
#include <stdint.h>

// ---------------- problem constants ----------------
#define DD    768
#define SS    1024
#define BB    4
#define LL    12
#define HH    12
#define HSZ   64
#define VV    32000
#define MR    (BB*SS)        // 4096 rows
#define QKVN  (3*DD)         // 2304
#define FF1   (4*DD)         // 3072
#define FF2   (3*DD)         // 2304
#define INV_SQRT_D 0.03608439182435161f
#define INV_SQRT_HS 0.125f

typedef __nv_bfloat16 bf16;

// ---------------- scratch (device globals; no allocs) ----------------
__device__ float g_x   [MR*DD];
__device__ float g_qkv [MR*QKVN];
__device__ float g_loss_sum;

// activation hi/lo pairs ([M][K] row-major)
__device__ bf16 g_h_h [MR*DD],  g_h_l [MR*DD];
__device__ bf16 g_o_h [MR*DD],  g_o_l [MR*DD];
__device__ bf16 g_f1_h[MR*FF1], g_f1_l[MR*FF1];
__device__ bf16 g_f2_h[MR*FF2], g_f2_l[MR*FF2];

// weight hi/lo pairs, ALL stored [N][K] row-major
__device__ bf16 g_Wqkv_h[LL*QKVN*DD], g_Wqkv_l[LL*QKVN*DD];
__device__ bf16 g_Wo_h [LL*DD*DD],    g_Wo_l [LL*DD*DD];
__device__ bf16 g_W1_h [LL*FF1*DD],   g_W1_l [LL*FF1*DD];
__device__ bf16 g_W2_h [LL*FF2*FF1],  g_W2_l [LL*FF2*FF1];
__device__ bf16 g_W3_h [LL*DD*FF2],   g_W3_l [LL*DD*FF2];
__device__ bf16 g_tok_h[VV*DD],       g_tok_l[VV*DD];
__device__ float g_bqkv[LL*QKVN];

// ---------------- helpers ----------------
__device__ __forceinline__ float gelu_exact(float v) {
    return 0.5f * v * (1.0f + erff(v * 0.70710678118654752f));
}
__device__ __forceinline__ void split2(float v, bf16& hi, bf16& lo) {
    hi = __float2bfloat16_rn(v);
    lo = __float2bfloat16_rn(v - __bfloat162float(hi));
}
__device__ __forceinline__ uint32_t smem_u32(const void* p) {
    uint32_t a;
    asm("{ .reg .u64 t; cvta.to.shared.u64 t, %1; cvt.u32.u64 %0, t; }" : "=r"(a) : "l"(p));
    return a;
}
__device__ __forceinline__ void cp_async16(uint32_t dst, const void* src) {
    asm volatile("cp.async.cg.shared.global [%0], [%1], 16;\n" :: "r"(dst), "l"(src));
}
__device__ __forceinline__ void cp_commit() {
    asm volatile("cp.async.commit_group;\n" ::: "memory");
}
__device__ __forceinline__ void cp_wait1() {
    asm volatile("cp.async.wait_group 1;\n" ::: "memory");
}

__device__ __forceinline__ void ldsm4(uint32_t addr, uint32_t& r0, uint32_t& r1,
                                      uint32_t& r2, uint32_t& r3) {
    asm volatile("ldmatrix.sync.aligned.m8n8.x4.shared.b16 {%0,%1,%2,%3}, [%4];"
                 : "=r"(r0), "=r"(r1), "=r"(r2), "=r"(r3) : "r"(addr));
}

__device__ __forceinline__ void mma_bf16(float* d, const uint32_t* a,
                                         uint32_t b0, uint32_t b1) {
    asm volatile(
        "mma.sync.aligned.m16n8k16.row.col.f32.bf16.bf16.f32 "
        "{%0,%1,%2,%3}, {%4,%5,%6,%7}, {%8,%9}, {%0,%1,%2,%3};\n"
        : "+f"(d[0]), "+f"(d[1]), "+f"(d[2]), "+f"(d[3])
        : "r"(a[0]), "r"(a[1]), "r"(a[2]), "r"(a[3]), "r"(b0), "r"(b1));
}

// ---------------- weight prep ----------------
__global__ void split_k(const float* __restrict__ src, bf16* __restrict__ h,
                        bf16* __restrict__ l, long n) {
    long i = (long)blockIdx.x * blockDim.x + threadIdx.x;
    if (i >= n) return;
    bf16 hi, lo; split2(src[i], hi, lo);
    h[i] = hi; l[i] = lo;
}

// transpose + split: src [L][K][N] f32 -> dst [L][N][K] hi/lo bf16
__global__ void tsplit_k(const float* __restrict__ src, bf16* __restrict__ h,
                         bf16* __restrict__ l, int K, int N) {
    __shared__ float t[32][33];
    int nb = blockIdx.x * 32, kb = blockIdx.y * 32, li = blockIdx.z;
    const float* s = src + (long)li*K*N;
    #pragma unroll
    for (int j = 0; j < 4; j++) {
        int k = kb + threadIdx.y + j*8;
        t[threadIdx.y + j*8][threadIdx.x] = s[(long)k*N + nb + threadIdx.x];
    }
    __syncthreads();
    #pragma unroll
    for (int j = 0; j < 4; j++) {
        int n = nb + threadIdx.y + j*8;
        int k = kb + threadIdx.x;
        float v = t[threadIdx.x][threadIdx.y + j*8];
        bf16 hi, lo; split2(v, hi, lo);
        long o = ((long)li*N + n)*K + k;
        h[o] = hi; l[o] = lo;
    }
}

// pack Wq/Wk/Wv [L][H][D][HS] -> [L][n=3*D][k=D] hi/lo
__global__ void pack_qkv_w(const float* __restrict__ Wq, const float* __restrict__ Wk,
                           const float* __restrict__ Wv,
                           bf16* __restrict__ Wph, bf16* __restrict__ Wpl) {
    long i = (long)blockIdx.x * blockDim.x + threadIdx.x;
    long total = (long)LL * QKVN * DD;
    if (i >= total) return;
    int d = (int)(i % DD);
    long rem = i / DD;
    int c = (int)(rem % QKVN);
    int l = (int)(rem / QKVN);
    int which = c / DD;
    int ce = c % DD;
    int h = ce / HSZ;
    int e = ce % HSZ;
    const float* W = (which == 0) ? Wq : (which == 1) ? Wk : Wv;
    float v = W[(((long)l*HH + h)*DD + d)*HSZ + e];
    bf16 hi, lo; split2(v, hi, lo);
    Wph[i] = hi; Wpl[i] = lo;
}

__global__ void pack_qkv_b(const float* __restrict__ bq, const float* __restrict__ bk,
                           const float* __restrict__ bv, float* __restrict__ bp) {
    int i = blockIdx.x * blockDim.x + threadIdx.x;
    if (i >= LL*QKVN) return;
    int c = i % QKVN;
    int l = i / QKVN;
    int which = c / DD;
    int ce = c % DD;
    int h = ce / HSZ;
    int e = ce % HSZ;
    const float* b = (which == 0) ? bq : (which == 1) ? bk : bv;
    bp[i] = b[((long)l*HH + h)*HSZ + e];
}

// ---------------- embedding ----------------
__global__ void embed_k(const int* __restrict__ idx, const float* __restrict__ tok,
                        const float* __restrict__ pos, float* __restrict__ x) {
    long i = (long)blockIdx.x * blockDim.x + threadIdx.x;
    if (i >= (long)MR*DD) return;
    int d = (int)(i % DD);
    int r = (int)(i / DD);
    int s = r & (SS - 1);
    x[i] = tok[(long)idx[r]*DD + d] + pos[(long)s*DD + d] * INV_SQRT_D;
}

// ---------------- layernorm -> hi/lo bf16 ----------------
__global__ __launch_bounds__(256)
void layernorm_k(const float* __restrict__ in, bf16* __restrict__ outh,
                 bf16* __restrict__ outl,
                 const float* __restrict__ gamma, const float* __restrict__ beta) {
    int row = blockIdx.x;
    int tid = threadIdx.x;
    const float* xr = in + (long)row*DD;
    float v0 = xr[tid], v1 = xr[tid+256], v2 = xr[tid+512];
    float s = v0+v1+v2;
    float q = v0*v0 + v1*v1 + v2*v2;
    __shared__ float sm[16];
    #pragma unroll
    for (int off = 16; off > 0; off >>= 1) {
        s += __shfl_xor_sync(0xffffffffu, s, off);
        q += __shfl_xor_sync(0xffffffffu, q, off);
    }
    int warp = tid >> 5, lane = tid & 31;
    if (lane == 0) { sm[warp] = s; sm[warp+8] = q; }
    __syncthreads();
    if (tid < 32) {
        float ss = (lane < 8) ? sm[lane] : 0.f;
        float qq = (lane < 8) ? sm[lane+8] : 0.f;
        #pragma unroll
        for (int off = 4; off > 0; off >>= 1) {
            ss += __shfl_xor_sync(0xffffffffu, ss, off);
            qq += __shfl_xor_sync(0xffffffffu, qq, off);
        }
        if (lane == 0) {
            float mu = ss * (1.0f/768.0f);
            float var = qq * (1.0f/768.0f) - mu*mu;
            sm[0] = mu;
            sm[1] = rsqrtf(var + 1e-5f);
        }
    }
    __syncthreads();
    float mu = sm[0], rs = sm[1];
    long base = (long)row*DD;
    #pragma unroll
    for (int p = 0; p < 3; p++) {
        int c = tid + p*256;
        float v = (p == 0) ? v0 : (p == 1) ? v1 : v2;
        float y = (v-mu)*rs*gamma[c] + beta[c];
        bf16 hi, lo; split2(y, hi, lo);
        outh[base + c] = hi; outl[base + c] = lo;
    }
}

// ====== mma.sync bf16 3-term GEMM: 128(M) x 256(N) tile, KC=32, 3 stages =====
// A: [M][K] hi/lo. B: [N][K] hi/lo (all K-major, non-trans ldmatrix only).
// EPI: 0 = +bias -> f32 ; 1 = gelu(+bias) -> hi/lo bf16 ; 2 = resid+scale*(acc+bias)
//      -> f32 ; 3 = plain -> f32
#define KC    32
#define KPAD  40                      // row stride elems: 80B -> conflict-free ldsm
#define A_ST  (128*KPAD)              // elems per A sub-tile (10240B)
#define B_ST  (256*KPAD)              // elems per B sub-tile (20480B)
#define ASOFF(st,hl) (((st)*2 + (hl)) * (A_ST*2))
#define BSOFF(st,hl) (6*A_ST*2 + ((st)*2 + (hl)) * (B_ST*2))
#define GSMEM2 (6*A_ST*2 + 6*B_ST*2)  // 61440 + 122880 = 184320 B

template<int EPI>
__global__ __launch_bounds__(256, 1)
void bgemm_k(const bf16* __restrict__ Ah, const bf16* __restrict__ Al,
             const bf16* __restrict__ Bh, const bf16* __restrict__ Bl,
             const float* __restrict__ bias, float* __restrict__ C,
             bf16* __restrict__ Ch, bf16* __restrict__ Cl,
             const float* __restrict__ resid, const float* __restrict__ scale_p,
             int M, int N, int K) {
    extern __shared__ char smem[];
    const uint32_t sb = smem_u32(smem);
    const int tid  = threadIdx.x;
    const int bm   = blockIdx.y, bn = blockIdx.x;
    const int warp = tid >> 5, lane = tid & 31;
    const int wm   = warp >> 2, wn = warp & 3;      // 2x4 warp grid, 64x64 per warp
    const int g    = lane >> 2, tg = lane & 3;
    const int lt   = lane >> 3, lrow = lane & 7;

    const bf16* Abh = Ah + (long)bm*128*K;
    const bf16* Abl = Al + (long)bm*128*K;
    const bf16* Bbh = Bh + (long)bn*256*K;
    const bf16* Bbl = Bl + (long)bn*256*K;

    float acc[4][8][4];
    #pragma unroll
    for (int mi = 0; mi < 4; mi++)
        #pragma unroll
        for (int ni = 0; ni < 8; ni++)
            #pragma unroll
            for (int v = 0; v < 4; v++) acc[mi][ni][v] = 0.f;

    const int nsteps = K / KC;

    auto issue = [&](int s) {
        const int st = s % 3;
        const long k0 = (long)s * KC;
        // A: 128 rows x 4 chunks (16B) per hi/lo
        for (int i = tid; i < 512; i += 256) {
            int r = i >> 2, ch = i & 3;
            uint32_t o = (uint32_t)(r*(KPAD*2) + ch*16);
            cp_async16(sb + ASOFF(st,0) + o, Abh + (long)r*K + k0 + ch*8);
            cp_async16(sb + ASOFF(st,1) + o, Abl + (long)r*K + k0 + ch*8);
        }
        // B: 256 rows x 4 chunks per hi/lo
        for (int i = tid; i < 1024; i += 256) {
            int r = i >> 2, ch = i & 3;
            uint32_t o = (uint32_t)(r*(KPAD*2) + ch*16);
            cp_async16(sb + BSOFF(st,0) + o, Bbh + (long)r*K + k0 + ch*8);
            cp_async16(sb + BSOFF(st,1) + o, Bbl + (long)r*K + k0 + ch*8);
        }
        cp_commit();
    };

    issue(0);
    issue(1);

    for (int s = 0; s < nsteps; s++) {
        cp_wait1();
        __syncthreads();
        if (s + 2 < nsteps) issue(s + 2);
        else cp_commit();                // empty group keeps wait_group 1 positional

        const int st = s % 3;
        const uint32_t a_h = sb + ASOFF(st,0), a_l = sb + ASOFF(st,1);
        const uint32_t b_h = sb + BSOFF(st,0), b_l = sb + BSOFF(st,1);

        #pragma unroll
        for (int kc = 0; kc < KC; kc += 16) {
            uint32_t fah[4][4], fal[4][4];
            #pragma unroll
            for (int mi = 0; mi < 4; mi++) {
                int row = wm*64 + mi*16 + (lt & 1)*8 + lrow;
                uint32_t o = (uint32_t)(row*(KPAD*2) + (kc + (lt >> 1)*8)*2);
                ldsm4(a_h + o, fah[mi][0], fah[mi][1], fah[mi][2], fah[mi][3]);
                ldsm4(a_l + o, fal[mi][0], fal[mi][1], fal[mi][2], fal[mi][3]);
            }
            #pragma unroll
            for (int gi = 0; gi < 4; gi++) {
                int row = wn*64 + gi*16 + (lt & 1)*8 + lrow;
                uint32_t o = (uint32_t)(row*(KPAD*2) + (kc + (lt >> 1)*8)*2);
                uint32_t bh[4], bl[4];
                ldsm4(b_h + o, bh[0], bh[1], bh[2], bh[3]);
                ldsm4(b_l + o, bl[0], bl[1], bl[2], bl[3]);
                { uint32_t t = bh[1]; bh[1] = bh[2]; bh[2] = t; }
                { uint32_t t = bl[1]; bl[1] = bl[2]; bl[2] = t; }
                // term Ah*Bh
                #pragma unroll
                for (int blk = 0; blk < 2; blk++) {
                    int ni = gi*2 + blk;
                    #pragma unroll
                    for (int mi = 0; mi < 4; mi++)
                        mma_bf16(acc[mi][ni], fah[mi], bh[blk*2], bh[blk*2+1]);
                }
                // term Ah*Bl
                #pragma unroll
                for (int blk = 0; blk < 2; blk++) {
                    int ni = gi*2 + blk;
                    #pragma unroll
                    for (int mi = 0; mi < 4; mi++)
                        mma_bf16(acc[mi][ni], fah[mi], bl[blk*2], bl[blk*2+1]);
                }
                // term Al*Bh
                #pragma unroll
                for (int blk = 0; blk < 2; blk++) {
                    int ni = gi*2 + blk;
                    #pragma unroll
                    for (int mi = 0; mi < 4; mi++)
                        mma_bf16(acc[mi][ni], fal[mi], bh[blk*2], bh[blk*2+1]);
                }
            }
        }
    }

    // ---------------- epilogue ----------------
    float scale = (EPI == 2) ? *scale_p : 0.f;
    #pragma unroll
    for (int mi = 0; mi < 4; mi++) {
        #pragma unroll
        for (int ni = 0; ni < 8; ni++) {
            int r0 = bm*128 + wm*64 + mi*16 + g;
            int c  = bn*256 + wn*64 + ni*8 + 2*tg;
            float2 bval = make_float2(0.f, 0.f);
            if (EPI != 3) bval = *(const float2*)(bias + c);
            #pragma unroll
            for (int half = 0; half < 2; half++) {
                long r = r0 + half*8;
                float v0 = acc[mi][ni][half*2    ] + bval.x;
                float v1 = acc[mi][ni][half*2 + 1] + bval.y;
                if (EPI == 1) {
                    v0 = gelu_exact(v0); v1 = gelu_exact(v1);
                    bf16 h0, l0, h1, l1;
                    split2(v0, h0, l0); split2(v1, h1, l1);
                    __nv_bfloat162 ph; ph.x = h0; ph.y = h1;
                    __nv_bfloat162 pl; pl.x = l0; pl.y = l1;
                    *(__nv_bfloat162*)(Ch + r*(long)N + c) = ph;
                    *(__nv_bfloat162*)(Cl + r*(long)N + c) = pl;
                } else {
                    if (EPI == 2) {
                        float2 rv = *(const float2*)(resid + r*(long)N + c);
                        v0 = rv.x + scale*v0;
                        v1 = rv.y + scale*v1;
                    }
                    float2 w = make_float2(v0, v1);
                    *(float2*)(C + r*(long)N + c) = w;
                }
            }
        }
    }
}

// ---------------- causal attention (flash-style, fp32) -> hi/lo out ----------
__global__ __launch_bounds__(64)
void attention_k(const float* __restrict__ qkv, bf16* __restrict__ oh,
                 bf16* __restrict__ ol) {
    const int mt = blockIdx.x;
    const int bh_ = blockIdx.y;
    const int b = bh_ / HH, h = bh_ % HH;
    const int tid = threadIdx.x;
    const int r = mt*64 + tid;
    const float* base = qkv + (long)(b*SS)*QKVN + h*HSZ;

    float q[64];
    {
        const float4* qp = (const float4*)(base + (long)r*QKVN);
        #pragma unroll
        for (int i = 0; i < 16; i++) {
            float4 t = qp[i];
            q[4*i] = t.x; q[4*i+1] = t.y; q[4*i+2] = t.z; q[4*i+3] = t.w;
        }
    }

    __shared__ float ks[64][64];
    __shared__ float vs[64][64];
    float m_i = -1e30f, l_i = 0.f;
    float acc[64];
    #pragma unroll
    for (int e = 0; e < 64; e++) acc[e] = 0.f;

    const int lr = tid >> 4;
    const int lc = (tid & 15) * 4;

    for (int kt = 0; kt <= mt; kt++) {
        __syncthreads();
        #pragma unroll
        for (int p = 0; p < 16; p++) {
            int row = p*4 + lr;
            const float* kp = base + (long)(kt*64 + row)*QKVN + DD + lc;
            const float* vp = base + (long)(kt*64 + row)*QKVN + 2*DD + lc;
            *(float4*)&ks[row][lc] = *(const float4*)kp;
            *(float4*)&vs[row][lc] = *(const float4*)vp;
        }
        __syncthreads();
        int tmax = (kt == mt) ? (tid + 1) : 64;
        for (int t = 0; t < tmax; t++) {
            float s = 0.f;
            #pragma unroll
            for (int d4 = 0; d4 < 16; d4++) {
                float4 kk = *(const float4*)&ks[t][d4*4];
                s += q[d4*4]*kk.x + q[d4*4+1]*kk.y + q[d4*4+2]*kk.z + q[d4*4+3]*kk.w;
            }
            s *= INV_SQRT_HS;
            if (s > m_i) {
                float corr = __expf(m_i - s);
                m_i = s;
                l_i = l_i*corr + 1.f;
                #pragma unroll
                for (int e4 = 0; e4 < 16; e4++) {
                    float4 vv = *(const float4*)&vs[t][e4*4];
                    acc[e4*4  ] = acc[e4*4  ]*corr + vv.x;
                    acc[e4*4+1] = acc[e4*4+1]*corr + vv.y;
                    acc[e4*4+2] = acc[e4*4+2]*corr + vv.z;
                    acc[e4*4+3] = acc[e4*4+3]*corr + vv.w;
                }
            } else {
                float p = __expf(s - m_i);
                l_i += p;
                #pragma unroll
                for (int e4 = 0; e4 < 16; e4++) {
                    float4 vv = *(const float4*)&vs[t][e4*4];
                    acc[e4*4  ] += p*vv.x;
                    acc[e4*4+1] += p*vv.y;
                    acc[e4*4+2] += p*vv.z;
                    acc[e4*4+3] += p*vv.w;
                }
            }
        }
    }

    float inv = 1.f / l_i;
    long obase = (long)(b*SS + r)*DD + h*HSZ;
    #pragma unroll
    for (int e = 0; e < 64; e++) {
        bf16 hi, lo; split2(acc[e]*inv, hi, lo);
        oh[obase + e] = hi; ol[obase + e] = lo;
    }
}

// ---------------- loss ----------------
__global__ void zero_loss_k() { g_loss_sum = 0.f; }

__global__ __launch_bounds__(256)
void loss_rows_k(const float* __restrict__ logits, const int* __restrict__ targets) {
    const int row = blockIdx.x;
    const int tid = threadIdx.x;
    const float* lr = logits + (long)row*VV;
    float m = -1e30f, l = 0.f;
    for (int c = tid; c < VV; c += 256) {
        float v = lr[c];
        if (v > m) { l = l*__expf(m - v) + 1.f; m = v; }
        else       { l += __expf(v - m); }
    }
    #pragma unroll
    for (int off = 16; off > 0; off >>= 1) {
        float m2 = __shfl_xor_sync(0xffffffffu, m, off);
        float l2 = __shfl_xor_sync(0xffffffffu, l, off);
        float M = fmaxf(m, m2);
        l = l*__expf(m - M) + l2*__expf(m2 - M);
        m = M;
    }
    __shared__ float sm_m[8], sm_l[8];
    int warp = tid >> 5, lane = tid & 31;
    if (lane == 0) { sm_m[warp] = m; sm_l[warp] = l; }
    __syncthreads();
    if (tid < 32) {
        float mm = (lane < 8) ? sm_m[lane] : -1e30f;
        float ll = (lane < 8) ? sm_l[lane] : 0.f;
        #pragma unroll
        for (int off = 4; off > 0; off >>= 1) {
            float m2 = __shfl_xor_sync(0xffffffffu, mm, off);
            float l2 = __shfl_xor_sync(0xffffffffu, ll, off);
            float M = fmaxf(mm, m2);
            ll = ll*__expf(mm - M) + l2*__expf(m2 - M);
            mm = M;
        }
        if (lane == 0) {
            float lse = logf(ll) + mm;
            int tgt = targets[row];
            atomicAdd(&g_loss_sum, lse - lr[tgt]);
        }
    }
}

__global__ void finalize_loss_k(float* __restrict__ out) {
    out[0] = g_loss_sum * (1.0f / (float)MR);
}

// ---------------- launch ----------------
extern "C" void kernel_launch(void* const* d_in, const int* in_sizes, int n_in,
                              void* d_out, int out_size) {
    const int*   idx     = (const int*)  d_in[0];
    const int*   targets = (const int*)  d_in[1];
    const float* tok     = (const float*)d_in[2];
    const float* pos     = (const float*)d_in[3];
    const float* Wq      = (const float*)d_in[4];
    const float* bq      = (const float*)d_in[5];
    const float* Wk      = (const float*)d_in[6];
    const float* bk      = (const float*)d_in[7];
    const float* Wv      = (const float*)d_in[8];
    const float* bv      = (const float*)d_in[9];
    const float* Wo      = (const float*)d_in[10];
    const float* bo      = (const float*)d_in[11];
    const float* ln1g    = (const float*)d_in[12];
    const float* ln1b    = (const float*)d_in[13];
    const float* ln2g    = (const float*)d_in[14];
    const float* ln2b    = (const float*)d_in[15];
    const float* W1      = (const float*)d_in[16];
    const float* b1      = (const float*)d_in[17];
    const float* W2      = (const float*)d_in[18];
    const float* b2      = (const float*)d_in[19];
    const float* W3      = (const float*)d_in[20];
    const float* b3      = (const float*)d_in[21];
    const float* att_s   = (const float*)d_in[22];
    const float* ffd_s   = (const float*)d_in[23];
    const float* lnfg    = (const float*)d_in[24];
    const float* lnfb    = (const float*)d_in[25];
    float* out = (float*)d_out;

    float *x, *qkvb, *bp;
    bf16 *hh, *hl, *oh, *ol, *f1h, *f1l, *f2h, *f2l;
    bf16 *Wqkvh, *Wqkvl, *Woh, *Wol, *W1h, *W1l, *W2h, *W2l, *W3h, *W3l, *tokh, *tokl;
    cudaGetSymbolAddress((void**)&x,    g_x);
    cudaGetSymbolAddress((void**)&qkvb, g_qkv);
    cudaGetSymbolAddress((void**)&bp,   g_bqkv);
    cudaGetSymbolAddress((void**)&hh,   g_h_h);   cudaGetSymbolAddress((void**)&hl,  g_h_l);
    cudaGetSymbolAddress((void**)&oh,   g_o_h);   cudaGetSymbolAddress((void**)&ol,  g_o_l);
    cudaGetSymbolAddress((void**)&f1h,  g_f1_h);  cudaGetSymbolAddress((void**)&f1l, g_f1_l);
    cudaGetSymbolAddress((void**)&f2h,  g_f2_h);  cudaGetSymbolAddress((void**)&f2l, g_f2_l);
    cudaGetSymbolAddress((void**)&Wqkvh,g_Wqkv_h);cudaGetSymbolAddress((void**)&Wqkvl,g_Wqkv_l);
    cudaGetSymbolAddress((void**)&Woh,  g_Wo_h);  cudaGetSymbolAddress((void**)&Wol, g_Wo_l);
    cudaGetSymbolAddress((void**)&W1h,  g_W1_h);  cudaGetSymbolAddress((void**)&W1l, g_W1_l);
    cudaGetSymbolAddress((void**)&W2h,  g_W2_h);  cudaGetSymbolAddress((void**)&W2l, g_W2_l);
    cudaGetSymbolAddress((void**)&W3h,  g_W3_h);  cudaGetSymbolAddress((void**)&W3l, g_W3_l);
    cudaGetSymbolAddress((void**)&tokh, g_tok_h); cudaGetSymbolAddress((void**)&tokl,g_tok_l);

    cudaFuncSetAttribute(bgemm_k<0>, cudaFuncAttributeMaxDynamicSharedMemorySize, GSMEM2);
    cudaFuncSetAttribute(bgemm_k<1>, cudaFuncAttributeMaxDynamicSharedMemorySize, GSMEM2);
    cudaFuncSetAttribute(bgemm_k<2>, cudaFuncAttributeMaxDynamicSharedMemorySize, GSMEM2);
    cudaFuncSetAttribute(bgemm_k<3>, cudaFuncAttributeMaxDynamicSharedMemorySize, GSMEM2);

    // weight prep (in-graph; deterministic). All weights -> [N][K] hi/lo bf16.
    {
        long n = (long)LL*QKVN*DD;
        pack_qkv_w<<<(unsigned)((n + 255)/256), 256>>>(Wq, Wk, Wv, Wqkvh, Wqkvl);
        pack_qkv_b<<<(LL*QKVN + 255)/256, 256>>>(bq, bk, bv, bp);
        tsplit_k<<<dim3(DD/32,  DD/32,  LL), dim3(32,8)>>>(Wo, Woh, Wol, DD,  DD);
        tsplit_k<<<dim3(FF1/32, DD/32,  LL), dim3(32,8)>>>(W1, W1h, W1l, DD,  FF1);
        tsplit_k<<<dim3(FF2/32, FF1/32, LL), dim3(32,8)>>>(W2, W2h, W2l, FF1, FF2);
        tsplit_k<<<dim3(DD/32,  FF2/32, LL), dim3(32,8)>>>(W3, W3h, W3l, FF2, DD);
        n = (long)VV*DD;
        split_k<<<(unsigned)((n+255)/256),256>>>(tok, tokh, tokl, n);
    }

    embed_k<<<(MR*DD + 255)/256, 256>>>(idx, tok, pos, x);

    for (int l = 0; l < LL; l++) {
        layernorm_k<<<MR, 256>>>(x, hh, hl, ln1g + (long)l*DD, ln1b + (long)l*DD);
        bgemm_k<0><<<dim3(QKVN/256, MR/128), 256, GSMEM2>>>(
            hh, hl, Wqkvh + (long)l*QKVN*DD, Wqkvl + (long)l*QKVN*DD,
            bp + (long)l*QKVN, qkvb, nullptr, nullptr, nullptr, nullptr,
            MR, QKVN, DD);
        attention_k<<<dim3(SS/64, BB*HH), 64>>>(qkvb, oh, ol);
        bgemm_k<2><<<dim3(DD/256, MR/128), 256, GSMEM2>>>(
            oh, ol, Woh + (long)l*DD*DD, Wol + (long)l*DD*DD,
            bo + (long)l*DD, x, nullptr, nullptr, x, att_s + l,
            MR, DD, DD);
        layernorm_k<<<MR, 256>>>(x, hh, hl, ln2g + (long)l*DD, ln2b + (long)l*DD);
        bgemm_k<1><<<dim3(FF1/256, MR/128), 256, GSMEM2>>>(
            hh, hl, W1h + (long)l*FF1*DD, W1l + (long)l*FF1*DD,
            b1 + (long)l*FF1, nullptr, f1h, f1l, nullptr, nullptr,
            MR, FF1, DD);
        bgemm_k<1><<<dim3(FF2/256, MR/128), 256, GSMEM2>>>(
            f1h, f1l, W2h + (long)l*FF2*FF1, W2l + (long)l*FF2*FF1,
            b2 + (long)l*FF2, nullptr, f2h, f2l, nullptr, nullptr,
            MR, FF2, FF1);
        bgemm_k<2><<<dim3(DD/256, MR/128), 256, GSMEM2>>>(
            f2h, f2l, W3h + (long)l*DD*FF2, W3l + (long)l*DD*FF2,
            b3 + (long)l*DD, x, nullptr, nullptr, x, ffd_s + l,
            MR, DD, FF2);
    }

    layernorm_k<<<MR, 256>>>(x, hh, hl, lnfg, lnfb);

    // logits = h @ tok^T -> directly into d_out (tok already [V][D] = [N][K])
    bgemm_k<3><<<dim3(VV/256, MR/128), 256, GSMEM2>>>(
        hh, hl, tokh, tokl, nullptr, out, nullptr, nullptr, nullptr, nullptr,
        MR, VV, DD);

    // loss
    zero_loss_k<<<1,1>>>();
    loss_rows_k<<<MR, 256>>>(out, targets);
    if (out_size > MR*(long)VV) {
        finalize_loss_k<<<1,1>>>(out + (long)MR*VV);
    }
}

// round 6
// speedup vs baseline: 1.0118x; 1.0118x over previous
#include <cuda_runtime.h>
#include <cuda_bf16.h>
#include <math.h>
#include <stdint.h>

// ---------------- problem constants ----------------
#define DD    768
#define SS    1024
#define BB    4
#define LL    12
#define HH    12
#define HSZ   64
#define VV    32000
#define MR    (BB*SS)        // 4096 rows
#define QKVN  (3*DD)         // 2304
#define FF1   (4*DD)         // 3072
#define FF2   (3*DD)         // 2304
#define INV_SQRT_D 0.03608439182435161f
#define INV_SQRT_HS 0.125f

typedef __nv_bfloat16 bf16;

// ---------------- scratch (device globals; no allocs) ----------------
__device__ float g_x   [MR*DD];
__device__ float g_qkv [MR*QKVN];
__device__ float g_loss_sum;

// activation hi/lo pairs ([M][K] row-major)
__device__ bf16 g_h_h [MR*DD],  g_h_l [MR*DD];
__device__ bf16 g_o_h [MR*DD],  g_o_l [MR*DD];
__device__ bf16 g_f1_h[MR*FF1], g_f1_l[MR*FF1];
__device__ bf16 g_f2_h[MR*FF2], g_f2_l[MR*FF2];

// weight hi/lo pairs, ALL stored [N][K] row-major
__device__ bf16 g_Wqkv_h[LL*QKVN*DD], g_Wqkv_l[LL*QKVN*DD];
__device__ bf16 g_Wo_h [LL*DD*DD],    g_Wo_l [LL*DD*DD];
__device__ bf16 g_W1_h [LL*FF1*DD],   g_W1_l [LL*FF1*DD];
__device__ bf16 g_W2_h [LL*FF2*FF1],  g_W2_l [LL*FF2*FF1];
__device__ bf16 g_W3_h [LL*DD*FF2],   g_W3_l [LL*DD*FF2];
__device__ bf16 g_tok_h[VV*DD],       g_tok_l[VV*DD];
__device__ float g_bqkv[LL*QKVN];

// ---------------- helpers ----------------
__device__ __forceinline__ float gelu_exact(float v) {
    return 0.5f * v * (1.0f + erff(v * 0.70710678118654752f));
}
__device__ __forceinline__ void split2(float v, bf16& hi, bf16& lo) {
    hi = __float2bfloat16_rn(v);
    lo = __float2bfloat16_rn(v - __bfloat162float(hi));
}
__device__ __forceinline__ uint32_t smem_u32(const void* p) {
    uint32_t a;
    asm("{ .reg .u64 t; cvta.to.shared.u64 t, %1; cvt.u32.u64 %0, t; }" : "=r"(a) : "l"(p));
    return a;
}
__device__ __forceinline__ void cp_async16(uint32_t dst, const void* src) {
    asm volatile("cp.async.cg.shared.global [%0], [%1], 16;\n" :: "r"(dst), "l"(src));
}
__device__ __forceinline__ void cp_commit() {
    asm volatile("cp.async.commit_group;\n" ::: "memory");
}
__device__ __forceinline__ void cp_wait1() {
    asm volatile("cp.async.wait_group 1;\n" ::: "memory");
}

__device__ __forceinline__ void ldsm4(uint32_t addr, uint32_t& r0, uint32_t& r1,
                                      uint32_t& r2, uint32_t& r3) {
    asm volatile("ldmatrix.sync.aligned.m8n8.x4.shared.b16 {%0,%1,%2,%3}, [%4];"
                 : "=r"(r0), "=r"(r1), "=r"(r2), "=r"(r3) : "r"(addr));
}

__device__ __forceinline__ void mma_bf16(float* d, const uint32_t* a,
                                         uint32_t b0, uint32_t b1) {
    asm volatile(
        "mma.sync.aligned.m16n8k16.row.col.f32.bf16.bf16.f32 "
        "{%0,%1,%2,%3}, {%4,%5,%6,%7}, {%8,%9}, {%0,%1,%2,%3};\n"
        : "+f"(d[0]), "+f"(d[1]), "+f"(d[2]), "+f"(d[3])
        : "r"(a[0]), "r"(a[1]), "r"(a[2]), "r"(a[3]), "r"(b0), "r"(b1));
}

// ---------------- weight prep ----------------
__global__ void split_k(const float* __restrict__ src, bf16* __restrict__ h,
                        bf16* __restrict__ l, long n) {
    long i = (long)blockIdx.x * blockDim.x + threadIdx.x;
    if (i >= n) return;
    bf16 hi, lo; split2(src[i], hi, lo);
    h[i] = hi; l[i] = lo;
}

// transpose + split: src [L][K][N] f32 -> dst [L][N][K] hi/lo bf16
__global__ void tsplit_k(const float* __restrict__ src, bf16* __restrict__ h,
                         bf16* __restrict__ l, int K, int N) {
    __shared__ float t[32][33];
    int nb = blockIdx.x * 32, kb = blockIdx.y * 32, li = blockIdx.z;
    const float* s = src + (long)li*K*N;
    #pragma unroll
    for (int j = 0; j < 4; j++) {
        int k = kb + threadIdx.y + j*8;
        t[threadIdx.y + j*8][threadIdx.x] = s[(long)k*N + nb + threadIdx.x];
    }
    __syncthreads();
    #pragma unroll
    for (int j = 0; j < 4; j++) {
        int n = nb + threadIdx.y + j*8;
        int k = kb + threadIdx.x;
        float v = t[threadIdx.x][threadIdx.y + j*8];
        bf16 hi, lo; split2(v, hi, lo);
        long o = ((long)li*N + n)*K + k;
        h[o] = hi; l[o] = lo;
    }
}

// pack Wq/Wk/Wv [L][H][D][HS] -> [L][n=3*D][k=D] hi/lo
__global__ void pack_qkv_w(const float* __restrict__ Wq, const float* __restrict__ Wk,
                           const float* __restrict__ Wv,
                           bf16* __restrict__ Wph, bf16* __restrict__ Wpl) {
    long i = (long)blockIdx.x * blockDim.x + threadIdx.x;
    long total = (long)LL * QKVN * DD;
    if (i >= total) return;
    int d = (int)(i % DD);
    long rem = i / DD;
    int c = (int)(rem % QKVN);
    int l = (int)(rem / QKVN);
    int which = c / DD;
    int ce = c % DD;
    int h = ce / HSZ;
    int e = ce % HSZ;
    const float* W = (which == 0) ? Wq : (which == 1) ? Wk : Wv;
    float v = W[(((long)l*HH + h)*DD + d)*HSZ + e];
    bf16 hi, lo; split2(v, hi, lo);
    Wph[i] = hi; Wpl[i] = lo;
}

__global__ void pack_qkv_b(const float* __restrict__ bq, const float* __restrict__ bk,
                           const float* __restrict__ bv, float* __restrict__ bp) {
    int i = blockIdx.x * blockDim.x + threadIdx.x;
    if (i >= LL*QKVN) return;
    int c = i % QKVN;
    int l = i / QKVN;
    int which = c / DD;
    int ce = c % DD;
    int h = ce / HSZ;
    int e = ce % HSZ;
    const float* b = (which == 0) ? bq : (which == 1) ? bk : bv;
    bp[i] = b[((long)l*HH + h)*HSZ + e];
}

// ---------------- embedding ----------------
__global__ void embed_k(const int* __restrict__ idx, const float* __restrict__ tok,
                        const float* __restrict__ pos, float* __restrict__ x) {
    long i = (long)blockIdx.x * blockDim.x + threadIdx.x;
    if (i >= (long)MR*DD) return;
    int d = (int)(i % DD);
    int r = (int)(i / DD);
    int s = r & (SS - 1);
    x[i] = tok[(long)idx[r]*DD + d] + pos[(long)s*DD + d] * INV_SQRT_D;
}

// ---------------- layernorm -> hi/lo bf16 ----------------
__global__ __launch_bounds__(256)
void layernorm_k(const float* __restrict__ in, bf16* __restrict__ outh,
                 bf16* __restrict__ outl,
                 const float* __restrict__ gamma, const float* __restrict__ beta) {
    int row = blockIdx.x;
    int tid = threadIdx.x;
    const float* xr = in + (long)row*DD;
    float v0 = xr[tid], v1 = xr[tid+256], v2 = xr[tid+512];
    float s = v0+v1+v2;
    float q = v0*v0 + v1*v1 + v2*v2;
    __shared__ float sm[16];
    #pragma unroll
    for (int off = 16; off > 0; off >>= 1) {
        s += __shfl_xor_sync(0xffffffffu, s, off);
        q += __shfl_xor_sync(0xffffffffu, q, off);
    }
    int warp = tid >> 5, lane = tid & 31;
    if (lane == 0) { sm[warp] = s; sm[warp+8] = q; }
    __syncthreads();
    if (tid < 32) {
        float ss = (lane < 8) ? sm[lane] : 0.f;
        float qq = (lane < 8) ? sm[lane+8] : 0.f;
        #pragma unroll
        for (int off = 4; off > 0; off >>= 1) {
            ss += __shfl_xor_sync(0xffffffffu, ss, off);
            qq += __shfl_xor_sync(0xffffffffu, qq, off);
        }
        if (lane == 0) {
            float mu = ss * (1.0f/768.0f);
            float var = qq * (1.0f/768.0f) - mu*mu;
            sm[0] = mu;
            sm[1] = rsqrtf(var + 1e-5f);
        }
    }
    __syncthreads();
    float mu = sm[0], rs = sm[1];
    long base = (long)row*DD;
    #pragma unroll
    for (int p = 0; p < 3; p++) {
        int c = tid + p*256;
        float v = (p == 0) ? v0 : (p == 1) ? v1 : v2;
        float y = (v-mu)*rs*gamma[c] + beta[c];
        bf16 hi, lo; split2(y, hi, lo);
        outh[base + c] = hi; outl[base + c] = lo;
    }
}

// ====== mma.sync bf16 3-term GEMM: 128x128 tile, KC=32, 2 stages, 2 CTA/SM ====
// A: [M][K] hi/lo. B: [N][K] hi/lo (K-major, non-trans ldmatrix only).
// EPI: 0 = +bias -> f32 ; 1 = gelu(+bias) -> hi/lo bf16 ; 2 = resid+scale*(acc+bias)
//      -> f32 ; 3 = plain -> f32
#define KC    32
#define KPAD  40                          // 80B row stride, conflict-free ldsm
#define T_ST  (128*KPAD)                  // elems per sub-tile
// arrays: 0=Ah 1=Al 2=Bh 3=Bl ; per stage
#define SOFF(st,a) ((((st)*4 + (a)) * T_ST) * 2)
#define GSMEM2 (2*4*T_ST*2)               // 81920 B

template<int EPI>
__global__ __launch_bounds__(256, 2)
void bgemm_k(const bf16* __restrict__ Ah, const bf16* __restrict__ Al,
             const bf16* __restrict__ Bh, const bf16* __restrict__ Bl,
             const float* __restrict__ bias, float* __restrict__ C,
             bf16* __restrict__ Ch, bf16* __restrict__ Cl,
             const float* __restrict__ resid, const float* __restrict__ scale_p,
             int M, int N, int K) {
    extern __shared__ char smem[];
    const uint32_t sb = smem_u32(smem);
    const int tid  = threadIdx.x;
    const int bm   = blockIdx.y, bn = blockIdx.x;
    const int warp = tid >> 5, lane = tid & 31;
    const int wm   = warp >> 1, wn = warp & 1;      // 4x2 warp grid, 32x64 per warp
    const int g    = lane >> 2, tg = lane & 3;
    const int lt   = lane >> 3, lrow = lane & 7;

    const bf16* Abh = Ah + (long)bm*128*K;
    const bf16* Abl = Al + (long)bm*128*K;
    const bf16* Bbh = Bh + (long)bn*128*K;
    const bf16* Bbl = Bl + (long)bn*128*K;

    float acc[2][8][4];
    #pragma unroll
    for (int mi = 0; mi < 2; mi++)
        #pragma unroll
        for (int ni = 0; ni < 8; ni++)
            #pragma unroll
            for (int v = 0; v < 4; v++) acc[mi][ni][v] = 0.f;

    const int nsteps = K / KC;

    auto issue = [&](int s) {
        const int st = s & 1;
        const long k0 = (long)s * KC;
        // each array: 128 rows x 4 chunks(16B) = 512 loads; 2 per thread
        #pragma unroll
        for (int p = 0; p < 2; p++) {
            int i = tid + p*256;
            int r = i >> 2, ch = i & 3;
            uint32_t o = (uint32_t)(r*(KPAD*2) + ch*16);
            long go = (long)r*K + k0 + ch*8;
            cp_async16(sb + SOFF(st,0) + o, Abh + go);
            cp_async16(sb + SOFF(st,1) + o, Abl + go);
            cp_async16(sb + SOFF(st,2) + o, Bbh + go);
            cp_async16(sb + SOFF(st,3) + o, Bbl + go);
        }
        cp_commit();
    };

    issue(0);

    for (int s = 0; s < nsteps; s++) {
        if (s + 1 < nsteps) issue(s + 1);
        else cp_commit();                  // empty group keeps wait positional
        cp_wait1();
        __syncthreads();

        const int st = s & 1;
        const uint32_t a_h = sb + SOFF(st,0), a_l = sb + SOFF(st,1);
        const uint32_t b_h = sb + SOFF(st,2), b_l = sb + SOFF(st,3);

        #pragma unroll
        for (int kc = 0; kc < KC; kc += 16) {
            uint32_t fah[2][4], fal[2][4];
            #pragma unroll
            for (int mi = 0; mi < 2; mi++) {
                int row = wm*32 + mi*16 + (lt & 1)*8 + lrow;
                uint32_t o = (uint32_t)(row*(KPAD*2) + (kc + (lt >> 1)*8)*2);
                ldsm4(a_h + o, fah[mi][0], fah[mi][1], fah[mi][2], fah[mi][3]);
                ldsm4(a_l + o, fal[mi][0], fal[mi][1], fal[mi][2], fal[mi][3]);
            }
            #pragma unroll
            for (int gi = 0; gi < 4; gi++) {
                int row = wn*64 + gi*16 + (lt & 1)*8 + lrow;
                uint32_t o = (uint32_t)(row*(KPAD*2) + (kc + (lt >> 1)*8)*2);
                uint32_t bh[4], bl[4];
                ldsm4(b_h + o, bh[0], bh[1], bh[2], bh[3]);
                ldsm4(b_l + o, bl[0], bl[1], bl[2], bl[3]);
                { uint32_t t = bh[1]; bh[1] = bh[2]; bh[2] = t; }
                { uint32_t t = bl[1]; bl[1] = bl[2]; bl[2] = t; }
                // term-major: acc reuse distance = 4 MMAs per term block
                #pragma unroll
                for (int blk = 0; blk < 2; blk++) {
                    int ni = gi*2 + blk;
                    #pragma unroll
                    for (int mi = 0; mi < 2; mi++)
                        mma_bf16(acc[mi][ni], fah[mi], bh[blk*2], bh[blk*2+1]);
                }
                #pragma unroll
                for (int blk = 0; blk < 2; blk++) {
                    int ni = gi*2 + blk;
                    #pragma unroll
                    for (int mi = 0; mi < 2; mi++)
                        mma_bf16(acc[mi][ni], fah[mi], bl[blk*2], bl[blk*2+1]);
                }
                #pragma unroll
                for (int blk = 0; blk < 2; blk++) {
                    int ni = gi*2 + blk;
                    #pragma unroll
                    for (int mi = 0; mi < 2; mi++)
                        mma_bf16(acc[mi][ni], fal[mi], bh[blk*2], bh[blk*2+1]);
                }
            }
        }
        __syncthreads();
    }

    // ---------------- epilogue ----------------
    float scale = (EPI == 2) ? *scale_p : 0.f;
    #pragma unroll
    for (int mi = 0; mi < 2; mi++) {
        #pragma unroll
        for (int ni = 0; ni < 8; ni++) {
            int r0 = bm*128 + wm*32 + mi*16 + g;
            int c  = bn*128 + wn*64 + ni*8 + 2*tg;
            float2 bval = make_float2(0.f, 0.f);
            if (EPI != 3) bval = *(const float2*)(bias + c);
            #pragma unroll
            for (int half = 0; half < 2; half++) {
                long r = r0 + half*8;
                float v0 = acc[mi][ni][half*2    ] + bval.x;
                float v1 = acc[mi][ni][half*2 + 1] + bval.y;
                if (EPI == 1) {
                    v0 = gelu_exact(v0); v1 = gelu_exact(v1);
                    bf16 h0, l0, h1, l1;
                    split2(v0, h0, l0); split2(v1, h1, l1);
                    __nv_bfloat162 ph; ph.x = h0; ph.y = h1;
                    __nv_bfloat162 pl; pl.x = l0; pl.y = l1;
                    *(__nv_bfloat162*)(Ch + r*(long)N + c) = ph;
                    *(__nv_bfloat162*)(Cl + r*(long)N + c) = pl;
                } else {
                    if (EPI == 2) {
                        float2 rv = *(const float2*)(resid + r*(long)N + c);
                        v0 = rv.x + scale*v0;
                        v1 = rv.y + scale*v1;
                    }
                    float2 w = make_float2(v0, v1);
                    *(float2*)(C + r*(long)N + c) = w;
                }
            }
        }
    }
}

// ---------------- causal attention (flash-style, fp32) -> hi/lo out ----------
__global__ __launch_bounds__(64)
void attention_k(const float* __restrict__ qkv, bf16* __restrict__ oh,
                 bf16* __restrict__ ol) {
    const int mt = blockIdx.x;
    const int bh_ = blockIdx.y;
    const int b = bh_ / HH, h = bh_ % HH;
    const int tid = threadIdx.x;
    const int r = mt*64 + tid;
    const float* base = qkv + (long)(b*SS)*QKVN + h*HSZ;

    float q[64];
    {
        const float4* qp = (const float4*)(base + (long)r*QKVN);
        #pragma unroll
        for (int i = 0; i < 16; i++) {
            float4 t = qp[i];
            q[4*i] = t.x; q[4*i+1] = t.y; q[4*i+2] = t.z; q[4*i+3] = t.w;
        }
    }

    __shared__ float ks[64][64];
    __shared__ float vs[64][64];
    float m_i = -1e30f, l_i = 0.f;
    float acc[64];
    #pragma unroll
    for (int e = 0; e < 64; e++) acc[e] = 0.f;

    const int lr = tid >> 4;
    const int lc = (tid & 15) * 4;

    for (int kt = 0; kt <= mt; kt++) {
        __syncthreads();
        #pragma unroll
        for (int p = 0; p < 16; p++) {
            int row = p*4 + lr;
            const float* kp = base + (long)(kt*64 + row)*QKVN + DD + lc;
            const float* vp = base + (long)(kt*64 + row)*QKVN + 2*DD + lc;
            *(float4*)&ks[row][lc] = *(const float4*)kp;
            *(float4*)&vs[row][lc] = *(const float4*)vp;
        }
        __syncthreads();
        int tmax = (kt == mt) ? (tid + 1) : 64;
        for (int t = 0; t < tmax; t++) {
            float s = 0.f;
            #pragma unroll
            for (int d4 = 0; d4 < 16; d4++) {
                float4 kk = *(const float4*)&ks[t][d4*4];
                s += q[d4*4]*kk.x + q[d4*4+1]*kk.y + q[d4*4+2]*kk.z + q[d4*4+3]*kk.w;
            }
            s *= INV_SQRT_HS;
            if (s > m_i) {
                float corr = __expf(m_i - s);
                m_i = s;
                l_i = l_i*corr + 1.f;
                #pragma unroll
                for (int e4 = 0; e4 < 16; e4++) {
                    float4 vv = *(const float4*)&vs[t][e4*4];
                    acc[e4*4  ] = acc[e4*4  ]*corr + vv.x;
                    acc[e4*4+1] = acc[e4*4+1]*corr + vv.y;
                    acc[e4*4+2] = acc[e4*4+2]*corr + vv.z;
                    acc[e4*4+3] = acc[e4*4+3]*corr + vv.w;
                }
            } else {
                float p = __expf(s - m_i);
                l_i += p;
                #pragma unroll
                for (int e4 = 0; e4 < 16; e4++) {
                    float4 vv = *(const float4*)&vs[t][e4*4];
                    acc[e4*4  ] += p*vv.x;
                    acc[e4*4+1] += p*vv.y;
                    acc[e4*4+2] += p*vv.z;
                    acc[e4*4+3] += p*vv.w;
                }
            }
        }
    }

    float inv = 1.f / l_i;
    long obase = (long)(b*SS + r)*DD + h*HSZ;
    #pragma unroll
    for (int e = 0; e < 64; e++) {
        bf16 hi, lo; split2(acc[e]*inv, hi, lo);
        oh[obase + e] = hi; ol[obase + e] = lo;
    }
}

// ---------------- loss ----------------
__global__ void zero_loss_k() { g_loss_sum = 0.f; }

__global__ __launch_bounds__(256)
void loss_rows_k(const float* __restrict__ logits, const int* __restrict__ targets) {
    const int row = blockIdx.x;
    const int tid = threadIdx.x;
    const float* lr = logits + (long)row*VV;
    float m = -1e30f, l = 0.f;
    for (int c = tid; c < VV; c += 256) {
        float v = lr[c];
        if (v > m) { l = l*__expf(m - v) + 1.f; m = v; }
        else       { l += __expf(v - m); }
    }
    #pragma unroll
    for (int off = 16; off > 0; off >>= 1) {
        float m2 = __shfl_xor_sync(0xffffffffu, m, off);
        float l2 = __shfl_xor_sync(0xffffffffu, l, off);
        float M = fmaxf(m, m2);
        l = l*__expf(m - M) + l2*__expf(m2 - M);
        m = M;
    }
    __shared__ float sm_m[8], sm_l[8];
    int warp = tid >> 5, lane = tid & 31;
    if (lane == 0) { sm_m[warp] = m; sm_l[warp] = l; }
    __syncthreads();
    if (tid < 32) {
        float mm = (lane < 8) ? sm_m[lane] : -1e30f;
        float ll = (lane < 8) ? sm_l[lane] : 0.f;
        #pragma unroll
        for (int off = 4; off > 0; off >>= 1) {
            float m2 = __shfl_xor_sync(0xffffffffu, mm, off);
            float l2 = __shfl_xor_sync(0xffffffffu, ll, off);
            float M = fmaxf(mm, m2);
            ll = ll*__expf(mm - M) + l2*__expf(m2 - M);
            mm = M;
        }
        if (lane == 0) {
            float lse = logf(ll) + mm;
            int tgt = targets[row];
            atomicAdd(&g_loss_sum, lse - lr[tgt]);
        }
    }
}

__global__ void finalize_loss_k(float* __restrict__ out) {
    out[0] = g_loss_sum * (1.0f / (float)MR);
}

// ---------------- launch ----------------
extern "C" void kernel_launch(void* const* d_in, const int* in_sizes, int n_in,
                              void* d_out, int out_size) {
    const int*   idx     = (const int*)  d_in[0];
    const int*   targets = (const int*)  d_in[1];
    const float* tok     = (const float*)d_in[2];
    const float* pos     = (const float*)d_in[3];
    const float* Wq      = (const float*)d_in[4];
    const float* bq      = (const float*)d_in[5];
    const float* Wk      = (const float*)d_in[6];
    const float* bk      = (const float*)d_in[7];
    const float* Wv      = (const float*)d_in[8];
    const float* bv      = (const float*)d_in[9];
    const float* Wo      = (const float*)d_in[10];
    const float* bo      = (const float*)d_in[11];
    const float* ln1g    = (const float*)d_in[12];
    const float* ln1b    = (const float*)d_in[13];
    const float* ln2g    = (const float*)d_in[14];
    const float* ln2b    = (const float*)d_in[15];
    const float* W1      = (const float*)d_in[16];
    const float* b1      = (const float*)d_in[17];
    const float* W2      = (const float*)d_in[18];
    const float* b2      = (const float*)d_in[19];
    const float* W3      = (const float*)d_in[20];
    const float* b3      = (const float*)d_in[21];
    const float* att_s   = (const float*)d_in[22];
    const float* ffd_s   = (const float*)d_in[23];
    const float* lnfg    = (const float*)d_in[24];
    const float* lnfb    = (const float*)d_in[25];
    float* out = (float*)d_out;

    float *x, *qkvb, *bp;
    bf16 *hh, *hl, *oh, *ol, *f1h, *f1l, *f2h, *f2l;
    bf16 *Wqkvh, *Wqkvl, *Woh, *Wol, *W1h, *W1l, *W2h, *W2l, *W3h, *W3l, *tokh, *tokl;
    cudaGetSymbolAddress((void**)&x,    g_x);
    cudaGetSymbolAddress((void**)&qkvb, g_qkv);
    cudaGetSymbolAddress((void**)&bp,   g_bqkv);
    cudaGetSymbolAddress((void**)&hh,   g_h_h);   cudaGetSymbolAddress((void**)&hl,  g_h_l);
    cudaGetSymbolAddress((void**)&oh,   g_o_h);   cudaGetSymbolAddress((void**)&ol,  g_o_l);
    cudaGetSymbolAddress((void**)&f1h,  g_f1_h);  cudaGetSymbolAddress((void**)&f1l, g_f1_l);
    cudaGetSymbolAddress((void**)&f2h,  g_f2_h);  cudaGetSymbolAddress((void**)&f2l, g_f2_l);
    cudaGetSymbolAddress((void**)&Wqkvh,g_Wqkv_h);cudaGetSymbolAddress((void**)&Wqkvl,g_Wqkv_l);
    cudaGetSymbolAddress((void**)&Woh,  g_Wo_h);  cudaGetSymbolAddress((void**)&Wol, g_Wo_l);
    cudaGetSymbolAddress((void**)&W1h,  g_W1_h);  cudaGetSymbolAddress((void**)&W1l, g_W1_l);
    cudaGetSymbolAddress((void**)&W2h,  g_W2_h);  cudaGetSymbolAddress((void**)&W2l, g_W2_l);
    cudaGetSymbolAddress((void**)&W3h,  g_W3_h);  cudaGetSymbolAddress((void**)&W3l, g_W3_l);
    cudaGetSymbolAddress((void**)&tokh, g_tok_h); cudaGetSymbolAddress((void**)&tokl,g_tok_l);

    cudaFuncSetAttribute(bgemm_k<0>, cudaFuncAttributeMaxDynamicSharedMemorySize, GSMEM2);
    cudaFuncSetAttribute(bgemm_k<1>, cudaFuncAttributeMaxDynamicSharedMemorySize, GSMEM2);
    cudaFuncSetAttribute(bgemm_k<2>, cudaFuncAttributeMaxDynamicSharedMemorySize, GSMEM2);
    cudaFuncSetAttribute(bgemm_k<3>, cudaFuncAttributeMaxDynamicSharedMemorySize, GSMEM2);

    // weight prep (in-graph; deterministic). All weights -> [N][K] hi/lo bf16.
    {
        long n = (long)LL*QKVN*DD;
        pack_qkv_w<<<(unsigned)((n + 255)/256), 256>>>(Wq, Wk, Wv, Wqkvh, Wqkvl);
        pack_qkv_b<<<(LL*QKVN + 255)/256, 256>>>(bq, bk, bv, bp);
        tsplit_k<<<dim3(DD/32,  DD/32,  LL), dim3(32,8)>>>(Wo, Woh, Wol, DD,  DD);
        tsplit_k<<<dim3(FF1/32, DD/32,  LL), dim3(32,8)>>>(W1, W1h, W1l, DD,  FF1);
        tsplit_k<<<dim3(FF2/32, FF1/32, LL), dim3(32,8)>>>(W2, W2h, W2l, FF1, FF2);
        tsplit_k<<<dim3(DD/32,  FF2/32, LL), dim3(32,8)>>>(W3, W3h, W3l, FF2, DD);
        n = (long)VV*DD;
        split_k<<<(unsigned)((n+255)/256),256>>>(tok, tokh, tokl, n);
    }

    embed_k<<<(MR*DD + 255)/256, 256>>>(idx, tok, pos, x);

    for (int l = 0; l < LL; l++) {
        layernorm_k<<<MR, 256>>>(x, hh, hl, ln1g + (long)l*DD, ln1b + (long)l*DD);
        bgemm_k<0><<<dim3(QKVN/128, MR/128), 256, GSMEM2>>>(
            hh, hl, Wqkvh + (long)l*QKVN*DD, Wqkvl + (long)l*QKVN*DD,
            bp + (long)l*QKVN, qkvb, nullptr, nullptr, nullptr, nullptr,
            MR, QKVN, DD);
        attention_k<<<dim3(SS/64, BB*HH), 64>>>(qkvb, oh, ol);
        bgemm_k<2><<<dim3(DD/128, MR/128), 256, GSMEM2>>>(
            oh, ol, Woh + (long)l*DD*DD, Wol + (long)l*DD*DD,
            bo + (long)l*DD, x, nullptr, nullptr, x, att_s + l,
            MR, DD, DD);
        layernorm_k<<<MR, 256>>>(x, hh, hl, ln2g + (long)l*DD, ln2b + (long)l*DD);
        bgemm_k<1><<<dim3(FF1/128, MR/128), 256, GSMEM2>>>(
            hh, hl, W1h + (long)l*FF1*DD, W1l + (long)l*FF1*DD,
            b1 + (long)l*FF1, nullptr, f1h, f1l, nullptr, nullptr,
            MR, FF1, DD);
        bgemm_k<1><<<dim3(FF2/128, MR/128), 256, GSMEM2>>>(
            f1h, f1l, W2h + (long)l*FF2*FF1, W2l + (long)l*FF2*FF1,
            b2 + (long)l*FF2, nullptr, f2h, f2l, nullptr, nullptr,
            MR, FF2, FF1);
        bgemm_k<2><<<dim3(DD/128, MR/128), 256, GSMEM2>>>(
            f2h, f2l, W3h + (long)l*DD*FF2, W3l + (long)l*DD*FF2,
            b3 + (long)l*DD, x, nullptr, nullptr, x, ffd_s + l,
            MR, DD, FF2);
    }

    layernorm_k<<<MR, 256>>>(x, hh, hl, lnfg, lnfb);

    // logits = h @ tok^T -> directly into d_out (tok already [V][D] = [N][K])
    bgemm_k<3><<<dim3(VV/128, MR/128), 256, GSMEM2>>>(
        hh, hl, tokh, tokl, nullptr, out, nullptr, nullptr, nullptr, nullptr,
        MR, VV, DD);

    // loss
    zero_loss_k<<<1,1>>>();
    loss_rows_k<<<MR, 256>>>(out, targets);
    if (out_size > MR*(long)VV) {
        finalize_loss_k<<<1,1>>>(out + (long)MR*VV);
    }
}

// round 7
// speedup vs baseline: 1.2033x; 1.1893x over previous
#include <cuda_runtime.h>
#include <cuda_bf16.h>
#include <math.h>
#include <stdint.h>

// ---------------- problem constants ----------------
#define DD    768
#define SS    1024
#define BB    4
#define LL    12
#define HH    12
#define HSZ   64
#define VV    32000
#define MR    (BB*SS)        // 4096
#define QKVN  (3*DD)         // 2304
#define FF1   (4*DD)         // 3072
#define FF2   (3*DD)         // 2304
#define INV_SQRT_D 0.03608439182435161f
#define INV_SQRT_HS 0.125f

typedef __nv_bfloat16 bf16;

// ---------------- scratch (device globals; no allocs) ----------------
__device__ float g_x   [MR*DD];
__device__ float g_qkv [MR*QKVN];
__device__ float g_actA[MR*FF2];     // h / o / f2 (tf32-rounded, k-permuted)
__device__ float g_actB[MR*FF1];     // f1
__device__ float g_loss_sum;

// tf32 weights, [N][K] row-major, k-permuted, stored as fp32
__device__ float g_Wqkv[LL*QKVN*DD];
__device__ float g_Wo [LL*DD*DD];
__device__ float g_W1 [LL*FF1*DD];
__device__ float g_W2 [LL*FF2*FF1];
__device__ float g_W3 [LL*DD*FF2];
__device__ float g_bqkv[LL*QKVN];

// bf16 3-term path for logits (natural layout)
__device__ bf16 g_h_h [MR*DD],  g_h_l [MR*DD];
__device__ bf16 g_tok_h[VV*DD], g_tok_l[VV*DD];

// ---------------- helpers ----------------
__device__ __forceinline__ float gelu_exact(float v) {
    return 0.5f * v * (1.0f + erff(v * 0.70710678118654752f));
}
__device__ __forceinline__ float f2tf_f(float x) {
    uint32_t u;
    asm("cvt.rna.tf32.f32 %0, %1;" : "=r"(u) : "f"(x));
    return __uint_as_float(u);
}
__device__ __forceinline__ void split2(float v, bf16& hi, bf16& lo) {
    hi = __float2bfloat16_rn(v);
    lo = __float2bfloat16_rn(v - __bfloat162float(hi));
}
// within-8 k permutation: j -> 2*(j&3) + (j>>2)
__device__ __forceinline__ int perm8(int c) {
    return (c & ~7) + 2*(c & 3) + ((c & 7) >> 2);
}
__device__ __forceinline__ uint32_t smem_u32(const void* p) {
    uint32_t a;
    asm("{ .reg .u64 t; cvta.to.shared.u64 t, %1; cvt.u32.u64 %0, t; }" : "=r"(a) : "l"(p));
    return a;
}
__device__ __forceinline__ void cp_async16(uint32_t dst, const void* src) {
    asm volatile("cp.async.cg.shared.global [%0], [%1], 16;\n" :: "r"(dst), "l"(src));
}
__device__ __forceinline__ void cp_commit() {
    asm volatile("cp.async.commit_group;\n" ::: "memory");
}
__device__ __forceinline__ void cp_wait1() {
    asm volatile("cp.async.wait_group 1;\n" ::: "memory");
}
__device__ __forceinline__ void ldsm4(uint32_t addr, uint32_t& r0, uint32_t& r1,
                                      uint32_t& r2, uint32_t& r3) {
    asm volatile("ldmatrix.sync.aligned.m8n8.x4.shared.b16 {%0,%1,%2,%3}, [%4];"
                 : "=r"(r0), "=r"(r1), "=r"(r2), "=r"(r3) : "r"(addr));
}
__device__ __forceinline__ void mma_tf32(float* d,
                                         uint32_t a0, uint32_t a1, uint32_t a2, uint32_t a3,
                                         uint32_t b0, uint32_t b1) {
    asm volatile(
        "mma.sync.aligned.m16n8k8.row.col.f32.tf32.tf32.f32 "
        "{%0,%1,%2,%3}, {%4,%5,%6,%7}, {%8,%9}, {%0,%1,%2,%3};\n"
        : "+f"(d[0]), "+f"(d[1]), "+f"(d[2]), "+f"(d[3])
        : "r"(a0), "r"(a1), "r"(a2), "r"(a3), "r"(b0), "r"(b1));
}
__device__ __forceinline__ void mma_bf16(float* d, const uint32_t* a,
                                         uint32_t b0, uint32_t b1) {
    asm volatile(
        "mma.sync.aligned.m16n8k16.row.col.f32.bf16.bf16.f32 "
        "{%0,%1,%2,%3}, {%4,%5,%6,%7}, {%8,%9}, {%0,%1,%2,%3};\n"
        : "+f"(d[0]), "+f"(d[1]), "+f"(d[2]), "+f"(d[3])
        : "r"(a[0]), "r"(a[1]), "r"(a[2]), "r"(a[3]), "r"(b0), "r"(b1));
}

// ---------------- weight prep ----------------
// Wq/Wk/Wv [L][H][D][HS] -> [L][n=3D][k=D] tf32 fp32, k-permuted
__global__ void pack_qkv_w_t(const float* __restrict__ Wq, const float* __restrict__ Wk,
                             const float* __restrict__ Wv, float* __restrict__ Wp) {
    long i = (long)blockIdx.x * blockDim.x + threadIdx.x;
    long total = (long)LL * QKVN * DD;
    if (i >= total) return;
    int d_store = (int)(i % DD);
    long rem = i / DD;
    int c = (int)(rem % QKVN);
    int l = (int)(rem / QKVN);
    // inverse perm: store position p holds source j = 4*(p&1) + ((p&7)>>1)
    int d = (d_store & ~7) + 4*(d_store & 1) + ((d_store & 7) >> 1);
    int which = c / DD;
    int ce = c % DD;
    int h = ce / HSZ;
    int e = ce % HSZ;
    const float* W = (which == 0) ? Wq : (which == 1) ? Wk : Wv;
    Wp[i] = f2tf_f(W[(((long)l*HH + h)*DD + d)*HSZ + e]);
}

__global__ void pack_qkv_b(const float* __restrict__ bq, const float* __restrict__ bk,
                           const float* __restrict__ bv, float* __restrict__ bp) {
    int i = blockIdx.x * blockDim.x + threadIdx.x;
    if (i >= LL*QKVN) return;
    int c = i % QKVN;
    int l = i / QKVN;
    int which = c / DD;
    int ce = c % DD;
    int h = ce / HSZ;
    int e = ce % HSZ;
    const float* b = (which == 0) ? bq : (which == 1) ? bk : bv;
    bp[i] = b[((long)l*HH + h)*HSZ + e];
}

// transpose + round + k-perm: src [L][K][N] f32 -> dst [L][N][K] tf32 fp32
__global__ void wtrans_t(const float* __restrict__ src, float* __restrict__ dst,
                         int K, int N) {
    __shared__ float t[32][33];
    int nb = blockIdx.x * 32, kb = blockIdx.y * 32, li = blockIdx.z;
    const float* s = src + (long)li*K*N;
    #pragma unroll
    for (int j = 0; j < 4; j++) {
        int k = kb + threadIdx.y + j*8;
        t[threadIdx.y + j*8][threadIdx.x] = s[(long)k*N + nb + threadIdx.x];
    }
    __syncthreads();
    #pragma unroll
    for (int j = 0; j < 4; j++) {
        int n = nb + threadIdx.y + j*8;
        int k = kb + threadIdx.x;
        float v = t[threadIdx.x][threadIdx.y + j*8];
        dst[((long)li*N + n)*K + perm8(k)] = f2tf_f(v);
    }
}

// tok -> bf16 hi/lo (natural layout) for logits
__global__ void split_k(const float* __restrict__ src, bf16* __restrict__ h,
                        bf16* __restrict__ l, long n) {
    long i = (long)blockIdx.x * blockDim.x + threadIdx.x;
    if (i >= n) return;
    bf16 hi, lo; split2(src[i], hi, lo);
    h[i] = hi; l[i] = lo;
}

// ---------------- embedding ----------------
__global__ void embed_k(const int* __restrict__ idx, const float* __restrict__ tok,
                        const float* __restrict__ pos, float* __restrict__ x) {
    long i = (long)blockIdx.x * blockDim.x + threadIdx.x;
    if (i >= (long)MR*DD) return;
    int d = (int)(i % DD);
    int r = (int)(i / DD);
    int s = r & (SS - 1);
    x[i] = tok[(long)idx[r]*DD + d] + pos[(long)s*DD + d] * INV_SQRT_D;
}

// ---------------- layernorm (tf32-rounded, k-permuted fp32 out) ----------------
__global__ __launch_bounds__(256)
void layernorm_t(const float* __restrict__ in, float* __restrict__ out,
                 const float* __restrict__ gamma, const float* __restrict__ beta) {
    int row = blockIdx.x;
    int tid = threadIdx.x;
    const float* xr = in + (long)row*DD;
    float v0 = xr[tid], v1 = xr[tid+256], v2 = xr[tid+512];
    float s = v0+v1+v2;
    float q = v0*v0 + v1*v1 + v2*v2;
    __shared__ float sm[16];
    #pragma unroll
    for (int off = 16; off > 0; off >>= 1) {
        s += __shfl_xor_sync(0xffffffffu, s, off);
        q += __shfl_xor_sync(0xffffffffu, q, off);
    }
    int warp = tid >> 5, lane = tid & 31;
    if (lane == 0) { sm[warp] = s; sm[warp+8] = q; }
    __syncthreads();
    if (tid < 32) {
        float ss = (lane < 8) ? sm[lane] : 0.f;
        float qq = (lane < 8) ? sm[lane+8] : 0.f;
        #pragma unroll
        for (int off = 4; off > 0; off >>= 1) {
            ss += __shfl_xor_sync(0xffffffffu, ss, off);
            qq += __shfl_xor_sync(0xffffffffu, qq, off);
        }
        if (lane == 0) {
            float mu = ss * (1.0f/768.0f);
            float var = qq * (1.0f/768.0f) - mu*mu;
            sm[0] = mu;
            sm[1] = rsqrtf(var + 1e-5f);
        }
    }
    __syncthreads();
    float mu = sm[0], rs = sm[1];
    long base = (long)row*DD;
    #pragma unroll
    for (int p = 0; p < 3; p++) {
        int c = tid + p*256;
        float v = (p == 0) ? v0 : (p == 1) ? v1 : v2;
        out[base + perm8(c)] = f2tf_f((v-mu)*rs*gamma[c] + beta[c]);
    }
}

// ---------------- final layernorm -> bf16 hi/lo (natural) ----------------
__global__ __launch_bounds__(256)
void layernorm_b(const float* __restrict__ in, bf16* __restrict__ outh,
                 bf16* __restrict__ outl,
                 const float* __restrict__ gamma, const float* __restrict__ beta) {
    int row = blockIdx.x;
    int tid = threadIdx.x;
    const float* xr = in + (long)row*DD;
    float v0 = xr[tid], v1 = xr[tid+256], v2 = xr[tid+512];
    float s = v0+v1+v2;
    float q = v0*v0 + v1*v1 + v2*v2;
    __shared__ float sm[16];
    #pragma unroll
    for (int off = 16; off > 0; off >>= 1) {
        s += __shfl_xor_sync(0xffffffffu, s, off);
        q += __shfl_xor_sync(0xffffffffu, q, off);
    }
    int warp = tid >> 5, lane = tid & 31;
    if (lane == 0) { sm[warp] = s; sm[warp+8] = q; }
    __syncthreads();
    if (tid < 32) {
        float ss = (lane < 8) ? sm[lane] : 0.f;
        float qq = (lane < 8) ? sm[lane+8] : 0.f;
        #pragma unroll
        for (int off = 4; off > 0; off >>= 1) {
            ss += __shfl_xor_sync(0xffffffffu, ss, off);
            qq += __shfl_xor_sync(0xffffffffu, qq, off);
        }
        if (lane == 0) {
            float mu = ss * (1.0f/768.0f);
            float var = qq * (1.0f/768.0f) - mu*mu;
            sm[0] = mu;
            sm[1] = rsqrtf(var + 1e-5f);
        }
    }
    __syncthreads();
    float mu = sm[0], rs = sm[1];
    long base = (long)row*DD;
    #pragma unroll
    for (int p = 0; p < 3; p++) {
        int c = tid + p*256;
        float v = (p == 0) ? v0 : (p == 1) ? v1 : v2;
        float y = (v-mu)*rs*gamma[c] + beta[c];
        bf16 hi, lo; split2(y, hi, lo);
        outh[base + c] = hi; outl[base + c] = lo;
    }
}

// ====== tf32 1-term GEMM: 128x128 tile, KC=16, 2 stages, conflict-free =======
// A [M][K], B [N][K]: tf32-rounded fp32, k-permuted (pairs tg/tg+4 adjacent).
// EPI: 0 = +bias -> fp32 natural ; 1 = gelu(+bias) -> tf32 fp32, k-perm store ;
//      2 = resid + scale*(acc+bias) -> fp32 natural
#define KCT   16
#define PADW  24                      // fp32 words per row (96B), conflict-free
#define T_STW (128*PADW)              // floats per sub-tile
#define GSMEMT (4*T_STW*4)            // 2 stages x (A+B) = 49152 B

template<int EPI>
__global__ __launch_bounds__(256, 2)
void tgemm_k(const float* __restrict__ A, const float* __restrict__ B,
             const float* __restrict__ bias, float* __restrict__ C,
             const float* __restrict__ resid, const float* __restrict__ scale_p,
             int M, int N, int K) {
    extern __shared__ char smem[];
    float* smf = (float*)smem;
    const uint32_t sb = smem_u32(smem);
    const int tid  = threadIdx.x;
    const int bm   = blockIdx.y, bn = blockIdx.x;
    const int warp = tid >> 5, lane = tid & 31;
    const int wm   = warp >> 1, wn = warp & 1;      // 4x2 grid, 32x64 per warp
    const int g    = lane >> 2, tg = lane & 3;

    const float* Ab = A + (long)bm*128*K;
    const float* Bb = B + (long)bn*128*K;

    float acc[2][8][4];
    #pragma unroll
    for (int mi = 0; mi < 2; mi++)
        #pragma unroll
        for (int ni = 0; ni < 8; ni++)
            #pragma unroll
            for (int v = 0; v < 4; v++) acc[mi][ni][v] = 0.f;

    const int nsteps = K / KCT;

    auto issue = [&](int s) {
        const int st = s & 1;
        const long k0 = (long)s * KCT;
        // A and B: 128 rows x 4 chunks(16B) each = 512 + 512; 2+2 per thread
        #pragma unroll
        for (int p = 0; p < 2; p++) {
            int i = tid + p*256;
            int r = i >> 2, ch = i & 3;
            uint32_t o = (uint32_t)((r*PADW + ch*4) * 4);
            cp_async16(sb + (st*2    )*T_STW*4 + o, Ab + (long)r*K + k0 + ch*4);
            cp_async16(sb + (st*2 + 1)*T_STW*4 + o, Bb + (long)r*K + k0 + ch*4);
        }
        cp_commit();
    };

    issue(0);

    for (int s = 0; s < nsteps; s++) {
        if (s + 1 < nsteps) issue(s + 1);
        else cp_commit();
        cp_wait1();
        __syncthreads();

        const int st = s & 1;
        const float* As = smf + (st*2    )*T_STW;
        const float* Bs = smf + (st*2 + 1)*T_STW;

        #pragma unroll
        for (int kc = 0; kc < KCT; kc += 8) {
            uint32_t fa[2][4];
            #pragma unroll
            for (int mi = 0; mi < 2; mi++) {
                int r0 = wm*32 + mi*16 + g;
                float2 aa = *(const float2*)&As[r0*PADW + kc + 2*tg];
                float2 ab = *(const float2*)&As[(r0+8)*PADW + kc + 2*tg];
                fa[mi][0] = __float_as_uint(aa.x);
                fa[mi][1] = __float_as_uint(ab.x);
                fa[mi][2] = __float_as_uint(aa.y);
                fa[mi][3] = __float_as_uint(ab.y);
            }
            #pragma unroll
            for (int ni = 0; ni < 8; ni++) {
                int n0 = wn*64 + ni*8 + g;
                float2 bb = *(const float2*)&Bs[n0*PADW + kc + 2*tg];
                uint32_t b0 = __float_as_uint(bb.x);
                uint32_t b1 = __float_as_uint(bb.y);
                #pragma unroll
                for (int mi = 0; mi < 2; mi++)
                    mma_tf32(acc[mi][ni], fa[mi][0], fa[mi][1], fa[mi][2], fa[mi][3], b0, b1);
            }
        }
        __syncthreads();
    }

    // ---------------- epilogue ----------------
    float scale = (EPI == 2) ? *scale_p : 0.f;
    #pragma unroll
    for (int mi = 0; mi < 2; mi++) {
        #pragma unroll
        for (int ni = 0; ni < 8; ni++) {
            int r0 = bm*128 + wm*32 + mi*16 + g;
            int c  = bn*128 + wn*64 + ni*8 + 2*tg;
            float2 bval = *(const float2*)(bias + c);
            #pragma unroll
            for (int half = 0; half < 2; half++) {
                long r = r0 + half*8;
                float v0 = acc[mi][ni][half*2    ] + bval.x;
                float v1 = acc[mi][ni][half*2 + 1] + bval.y;
                if (EPI == 1) {
                    C[r*(long)N + perm8(c)]     = f2tf_f(gelu_exact(v0));
                    C[r*(long)N + perm8(c + 1)] = f2tf_f(gelu_exact(v1));
                } else {
                    if (EPI == 2) {
                        float2 rv = *(const float2*)(resid + r*(long)N + c);
                        v0 = rv.x + scale*v0;
                        v1 = rv.y + scale*v1;
                    }
                    *(float2*)(C + r*(long)N + c) = make_float2(v0, v1);
                }
            }
        }
    }
}

// ====== bf16 3-term GEMM for logits (R6-validated, EPI=3 only) ===============
#define KC    32
#define KPAD  40
#define T_ST  (128*KPAD)
#define SOFF(st,a) ((((st)*4 + (a)) * T_ST) * 2)
#define GSMEM2 (2*4*T_ST*2)

__global__ __launch_bounds__(256, 2)
void bgemm_k(const bf16* __restrict__ Ah, const bf16* __restrict__ Al,
             const bf16* __restrict__ Bh, const bf16* __restrict__ Bl,
             float* __restrict__ C, int M, int N, int K) {
    extern __shared__ char smem[];
    const uint32_t sb = smem_u32(smem);
    const int tid  = threadIdx.x;
    const int bm   = blockIdx.y, bn = blockIdx.x;
    const int warp = tid >> 5, lane = tid & 31;
    const int wm   = warp >> 1, wn = warp & 1;
    const int g    = lane >> 2, tg = lane & 3;
    const int lt   = lane >> 3, lrow = lane & 7;

    const bf16* Abh = Ah + (long)bm*128*K;
    const bf16* Abl = Al + (long)bm*128*K;
    const bf16* Bbh = Bh + (long)bn*128*K;
    const bf16* Bbl = Bl + (long)bn*128*K;

    float acc[2][8][4];
    #pragma unroll
    for (int mi = 0; mi < 2; mi++)
        #pragma unroll
        for (int ni = 0; ni < 8; ni++)
            #pragma unroll
            for (int v = 0; v < 4; v++) acc[mi][ni][v] = 0.f;

    const int nsteps = K / KC;

    auto issue = [&](int s) {
        const int st = s & 1;
        const long k0 = (long)s * KC;
        #pragma unroll
        for (int p = 0; p < 2; p++) {
            int i = tid + p*256;
            int r = i >> 2, ch = i & 3;
            uint32_t o = (uint32_t)(r*(KPAD*2) + ch*16);
            long go = (long)r*K + k0 + ch*8;
            cp_async16(sb + SOFF(st,0) + o, Abh + go);
            cp_async16(sb + SOFF(st,1) + o, Abl + go);
            cp_async16(sb + SOFF(st,2) + o, Bbh + go);
            cp_async16(sb + SOFF(st,3) + o, Bbl + go);
        }
        cp_commit();
    };

    issue(0);

    for (int s = 0; s < nsteps; s++) {
        if (s + 1 < nsteps) issue(s + 1);
        else cp_commit();
        cp_wait1();
        __syncthreads();

        const int st = s & 1;
        const uint32_t a_h = sb + SOFF(st,0), a_l = sb + SOFF(st,1);
        const uint32_t b_h = sb + SOFF(st,2), b_l = sb + SOFF(st,3);

        #pragma unroll
        for (int kc = 0; kc < KC; kc += 16) {
            uint32_t fah[2][4], fal[2][4];
            #pragma unroll
            for (int mi = 0; mi < 2; mi++) {
                int row = wm*32 + mi*16 + (lt & 1)*8 + lrow;
                uint32_t o = (uint32_t)(row*(KPAD*2) + (kc + (lt >> 1)*8)*2);
                ldsm4(a_h + o, fah[mi][0], fah[mi][1], fah[mi][2], fah[mi][3]);
                ldsm4(a_l + o, fal[mi][0], fal[mi][1], fal[mi][2], fal[mi][3]);
            }
            #pragma unroll
            for (int gi = 0; gi < 4; gi++) {
                int row = wn*64 + gi*16 + (lt & 1)*8 + lrow;
                uint32_t o = (uint32_t)(row*(KPAD*2) + (kc + (lt >> 1)*8)*2);
                uint32_t bh[4], bl[4];
                ldsm4(b_h + o, bh[0], bh[1], bh[2], bh[3]);
                ldsm4(b_l + o, bl[0], bl[1], bl[2], bl[3]);
                { uint32_t t = bh[1]; bh[1] = bh[2]; bh[2] = t; }
                { uint32_t t = bl[1]; bl[1] = bl[2]; bl[2] = t; }
                #pragma unroll
                for (int blk = 0; blk < 2; blk++) {
                    int ni = gi*2 + blk;
                    #pragma unroll
                    for (int mi = 0; mi < 2; mi++)
                        mma_bf16(acc[mi][ni], fah[mi], bh[blk*2], bh[blk*2+1]);
                }
                #pragma unroll
                for (int blk = 0; blk < 2; blk++) {
                    int ni = gi*2 + blk;
                    #pragma unroll
                    for (int mi = 0; mi < 2; mi++)
                        mma_bf16(acc[mi][ni], fah[mi], bl[blk*2], bl[blk*2+1]);
                }
                #pragma unroll
                for (int blk = 0; blk < 2; blk++) {
                    int ni = gi*2 + blk;
                    #pragma unroll
                    for (int mi = 0; mi < 2; mi++)
                        mma_bf16(acc[mi][ni], fal[mi], bh[blk*2], bh[blk*2+1]);
                }
            }
        }
        __syncthreads();
    }

    #pragma unroll
    for (int mi = 0; mi < 2; mi++) {
        #pragma unroll
        for (int ni = 0; ni < 8; ni++) {
            int r0 = bm*128 + wm*32 + mi*16 + g;
            int c  = bn*128 + wn*64 + ni*8 + 2*tg;
            #pragma unroll
            for (int half = 0; half < 2; half++) {
                long r = r0 + half*8;
                *(float2*)(C + r*(long)N + c) =
                    make_float2(acc[mi][ni][half*2], acc[mi][ni][half*2+1]);
            }
        }
    }
}

// ---------------- causal attention -> tf32-rounded, k-permuted fp32 ----------
__global__ __launch_bounds__(64)
void attention_k(const float* __restrict__ qkv, float* __restrict__ o) {
    const int mt = blockIdx.x;
    const int bh_ = blockIdx.y;
    const int b = bh_ / HH, h = bh_ % HH;
    const int tid = threadIdx.x;
    const int r = mt*64 + tid;
    const float* base = qkv + (long)(b*SS)*QKVN + h*HSZ;

    float q[64];
    {
        const float4* qp = (const float4*)(base + (long)r*QKVN);
        #pragma unroll
        for (int i = 0; i < 16; i++) {
            float4 t = qp[i];
            q[4*i] = t.x; q[4*i+1] = t.y; q[4*i+2] = t.z; q[4*i+3] = t.w;
        }
    }

    __shared__ float ks[64][64];
    __shared__ float vs[64][64];
    float m_i = -1e30f, l_i = 0.f;
    float acc[64];
    #pragma unroll
    for (int e = 0; e < 64; e++) acc[e] = 0.f;

    const int lr = tid >> 4;
    const int lc = (tid & 15) * 4;

    for (int kt = 0; kt <= mt; kt++) {
        __syncthreads();
        #pragma unroll
        for (int p = 0; p < 16; p++) {
            int row = p*4 + lr;
            const float* kp = base + (long)(kt*64 + row)*QKVN + DD + lc;
            const float* vp = base + (long)(kt*64 + row)*QKVN + 2*DD + lc;
            *(float4*)&ks[row][lc] = *(const float4*)kp;
            *(float4*)&vs[row][lc] = *(const float4*)vp;
        }
        __syncthreads();
        int tmax = (kt == mt) ? (tid + 1) : 64;
        for (int t = 0; t < tmax; t++) {
            float s = 0.f;
            #pragma unroll
            for (int d4 = 0; d4 < 16; d4++) {
                float4 kk = *(const float4*)&ks[t][d4*4];
                s += q[d4*4]*kk.x + q[d4*4+1]*kk.y + q[d4*4+2]*kk.z + q[d4*4+3]*kk.w;
            }
            s *= INV_SQRT_HS;
            if (s > m_i) {
                float corr = __expf(m_i - s);
                m_i = s;
                l_i = l_i*corr + 1.f;
                #pragma unroll
                for (int e4 = 0; e4 < 16; e4++) {
                    float4 vv = *(const float4*)&vs[t][e4*4];
                    acc[e4*4  ] = acc[e4*4  ]*corr + vv.x;
                    acc[e4*4+1] = acc[e4*4+1]*corr + vv.y;
                    acc[e4*4+2] = acc[e4*4+2]*corr + vv.z;
                    acc[e4*4+3] = acc[e4*4+3]*corr + vv.w;
                }
            } else {
                float p = __expf(s - m_i);
                l_i += p;
                #pragma unroll
                for (int e4 = 0; e4 < 16; e4++) {
                    float4 vv = *(const float4*)&vs[t][e4*4];
                    acc[e4*4  ] += p*vv.x;
                    acc[e4*4+1] += p*vv.y;
                    acc[e4*4+2] += p*vv.z;
                    acc[e4*4+3] += p*vv.w;
                }
            }
        }
    }

    float inv = 1.f / l_i;
    long rowoff = (long)(b*SS + r)*DD;
    #pragma unroll
    for (int e = 0; e < 64; e++) {
        o[rowoff + h*HSZ + perm8(e)] = f2tf_f(acc[e]*inv);
    }
}

// ---------------- loss ----------------
__global__ void zero_loss_k() { g_loss_sum = 0.f; }

__global__ __launch_bounds__(256)
void loss_rows_k(const float* __restrict__ logits, const int* __restrict__ targets) {
    const int row = blockIdx.x;
    const int tid = threadIdx.x;
    const float* lr = logits + (long)row*VV;
    float m = -1e30f, l = 0.f;
    for (int c = tid; c < VV; c += 256) {
        float v = lr[c];
        if (v > m) { l = l*__expf(m - v) + 1.f; m = v; }
        else       { l += __expf(v - m); }
    }
    #pragma unroll
    for (int off = 16; off > 0; off >>= 1) {
        float m2 = __shfl_xor_sync(0xffffffffu, m, off);
        float l2 = __shfl_xor_sync(0xffffffffu, l, off);
        float M = fmaxf(m, m2);
        l = l*__expf(m - M) + l2*__expf(m2 - M);
        m = M;
    }
    __shared__ float sm_m[8], sm_l[8];
    int warp = tid >> 5, lane = tid & 31;
    if (lane == 0) { sm_m[warp] = m; sm_l[warp] = l; }
    __syncthreads();
    if (tid < 32) {
        float mm = (lane < 8) ? sm_m[lane] : -1e30f;
        float ll = (lane < 8) ? sm_l[lane] : 0.f;
        #pragma unroll
        for (int off = 4; off > 0; off >>= 1) {
            float m2 = __shfl_xor_sync(0xffffffffu, mm, off);
            float l2 = __shfl_xor_sync(0xffffffffu, ll, off);
            float M = fmaxf(mm, m2);
            ll = ll*__expf(mm - M) + l2*__expf(m2 - M);
            mm = M;
        }
        if (lane == 0) {
            float lse = logf(ll) + mm;
            int tgt = targets[row];
            atomicAdd(&g_loss_sum, lse - lr[tgt]);
        }
    }
}

__global__ void finalize_loss_k(float* __restrict__ out) {
    out[0] = g_loss_sum * (1.0f / (float)MR);
}

// ---------------- launch ----------------
extern "C" void kernel_launch(void* const* d_in, const int* in_sizes, int n_in,
                              void* d_out, int out_size) {
    const int*   idx     = (const int*)  d_in[0];
    const int*   targets = (const int*)  d_in[1];
    const float* tok     = (const float*)d_in[2];
    const float* pos     = (const float*)d_in[3];
    const float* Wq      = (const float*)d_in[4];
    const float* bq      = (const float*)d_in[5];
    const float* Wk      = (const float*)d_in[6];
    const float* bk      = (const float*)d_in[7];
    const float* Wv      = (const float*)d_in[8];
    const float* bv      = (const float*)d_in[9];
    const float* Wo      = (const float*)d_in[10];
    const float* bo      = (const float*)d_in[11];
    const float* ln1g    = (const float*)d_in[12];
    const float* ln1b    = (const float*)d_in[13];
    const float* ln2g    = (const float*)d_in[14];
    const float* ln2b    = (const float*)d_in[15];
    const float* W1      = (const float*)d_in[16];
    const float* b1      = (const float*)d_in[17];
    const float* W2      = (const float*)d_in[18];
    const float* b2      = (const float*)d_in[19];
    const float* W3      = (const float*)d_in[20];
    const float* b3      = (const float*)d_in[21];
    const float* att_s   = (const float*)d_in[22];
    const float* ffd_s   = (const float*)d_in[23];
    const float* lnfg    = (const float*)d_in[24];
    const float* lnfb    = (const float*)d_in[25];
    float* out = (float*)d_out;

    float *x, *qkvb, *actA, *actB, *bp;
    float *Wqkvt, *Wot, *W1t, *W2t, *W3t;
    bf16 *hh, *hl, *tokh, *tokl;
    cudaGetSymbolAddress((void**)&x,     g_x);
    cudaGetSymbolAddress((void**)&qkvb,  g_qkv);
    cudaGetSymbolAddress((void**)&actA,  g_actA);
    cudaGetSymbolAddress((void**)&actB,  g_actB);
    cudaGetSymbolAddress((void**)&bp,    g_bqkv);
    cudaGetSymbolAddress((void**)&Wqkvt, g_Wqkv);
    cudaGetSymbolAddress((void**)&Wot,   g_Wo);
    cudaGetSymbolAddress((void**)&W1t,   g_W1);
    cudaGetSymbolAddress((void**)&W2t,   g_W2);
    cudaGetSymbolAddress((void**)&W3t,   g_W3);
    cudaGetSymbolAddress((void**)&hh,    g_h_h);
    cudaGetSymbolAddress((void**)&hl,    g_h_l);
    cudaGetSymbolAddress((void**)&tokh,  g_tok_h);
    cudaGetSymbolAddress((void**)&tokl,  g_tok_l);

    cudaFuncSetAttribute(tgemm_k<0>, cudaFuncAttributeMaxDynamicSharedMemorySize, GSMEMT);
    cudaFuncSetAttribute(tgemm_k<1>, cudaFuncAttributeMaxDynamicSharedMemorySize, GSMEMT);
    cudaFuncSetAttribute(tgemm_k<2>, cudaFuncAttributeMaxDynamicSharedMemorySize, GSMEMT);
    cudaFuncSetAttribute(bgemm_k,    cudaFuncAttributeMaxDynamicSharedMemorySize, GSMEM2);

    // ---- prep (in-graph; deterministic) ----
    {
        long n = (long)LL*QKVN*DD;
        pack_qkv_w_t<<<(unsigned)((n + 255)/256), 256>>>(Wq, Wk, Wv, Wqkvt);
        pack_qkv_b<<<(LL*QKVN + 255)/256, 256>>>(bq, bk, bv, bp);
        wtrans_t<<<dim3(DD/32,  DD/32,  LL), dim3(32,8)>>>(Wo, Wot, DD,  DD);
        wtrans_t<<<dim3(FF1/32, DD/32,  LL), dim3(32,8)>>>(W1, W1t, DD,  FF1);
        wtrans_t<<<dim3(FF2/32, FF1/32, LL), dim3(32,8)>>>(W2, W2t, FF1, FF2);
        wtrans_t<<<dim3(DD/32,  FF2/32, LL), dim3(32,8)>>>(W3, W3t, FF2, DD);
        n = (long)VV*DD;
        split_k<<<(unsigned)((n+255)/256),256>>>(tok, tokh, tokl, n);
    }

    embed_k<<<(MR*DD + 255)/256, 256>>>(idx, tok, pos, x);

    for (int l = 0; l < LL; l++) {
        layernorm_t<<<MR, 256>>>(x, actA, ln1g + (long)l*DD, ln1b + (long)l*DD);
        tgemm_k<0><<<dim3(QKVN/128, MR/128), 256, GSMEMT>>>(
            actA, Wqkvt + (long)l*QKVN*DD, bp + (long)l*QKVN, qkvb,
            nullptr, nullptr, MR, QKVN, DD);
        attention_k<<<dim3(SS/64, BB*HH), 64>>>(qkvb, actA);
        tgemm_k<2><<<dim3(DD/128, MR/128), 256, GSMEMT>>>(
            actA, Wot + (long)l*DD*DD, bo + (long)l*DD, x, x, att_s + l,
            MR, DD, DD);
        layernorm_t<<<MR, 256>>>(x, actA, ln2g + (long)l*DD, ln2b + (long)l*DD);
        tgemm_k<1><<<dim3(FF1/128, MR/128), 256, GSMEMT>>>(
            actA, W1t + (long)l*FF1*DD, b1 + (long)l*FF1, actB,
            nullptr, nullptr, MR, FF1, DD);
        tgemm_k<1><<<dim3(FF2/128, MR/128), 256, GSMEMT>>>(
            actB, W2t + (long)l*FF2*FF1, b2 + (long)l*FF2, actA,
            nullptr, nullptr, MR, FF2, FF1);
        tgemm_k<2><<<dim3(DD/128, MR/128), 256, GSMEMT>>>(
            actA, W3t + (long)l*DD*FF2, b3 + (long)l*DD, x, x, ffd_s + l,
            MR, DD, FF2);
    }

    // final LN -> bf16 hi/lo ; logits via 3-term bf16 (precision for the metric)
    layernorm_b<<<MR, 256>>>(x, hh, hl, lnfg, lnfb);
    bgemm_k<<<dim3(VV/128, MR/128), 256, GSMEM2>>>(
        hh, hl, tokh, tokl, out, MR, VV, DD);

    // loss
    zero_loss_k<<<1,1>>>();
    loss_rows_k<<<MR, 256>>>(out, targets);
    if (out_size > MR*(long)VV) {
        finalize_loss_k<<<1,1>>>(out + (long)MR*VV);
    }
}